// round 1
// baseline (speedup 1.0000x reference)
#include <cuda_runtime.h>

#define LOG2E 1.4426950408889634f
#define BB 16
#define LL 1024
#define FF 64
#define DD 256
#define SSn 2
#define NNn 16
#define HHn 32
#define MMn (BB*LL)
#define EPSV 1e-5f

// ---------------- scratch (device globals: no allocation allowed) ----------------
__device__ __align__(128) float g_Pd[SSn][FF][DD];
__device__ __align__(128) float g_Pt[SSn][FF][DD];
__device__ __align__(128) float g_PB[SSn][FF][NNn];
__device__ __align__(128) float g_PC[SSn][FF][NNn];
__device__ __align__(128) float g_pbd[SSn][DD];
__device__ __align__(128) float g_pbt[SSn][DD];
__device__ __align__(128) float g_pbB[SSn][NNn];
__device__ __align__(128) float g_pbC[SSn][NNn];
__device__ __align__(128) float g_A2[SSn][DD][NNn];
__device__ __align__(128) float g_h[MMn*DD];          // 16 MB
__device__ __align__(128) float g_delta[SSn][MMn*DD]; // 32 MB
__device__ __align__(128) float g_Bm[SSn][MMn*NNn];   // 2 MB
__device__ __align__(128) float g_state[SSn][BB][DD][NNn];

// ---------------- kernel 1: fold weights through W_in ----------------
// u = h@Wd + bd = x@(W_in@Wd) + (b_in@Wd + bd), etc.
__global__ void __launch_bounds__(256) precompute_kernel(
    const float* __restrict__ W_in, const float* __restrict__ b_in,
    const float* __restrict__ Wd, const float* __restrict__ bd,
    const float* __restrict__ WB, const float* __restrict__ WC,
    const float* __restrict__ Wtau, const float* __restrict__ A_log)
{
    int s = blockIdx.x >> 6;   // 0..1
    int f = blockIdx.x & 63;   // 0..63
    int e = threadIdx.x;       // 0..255
    const float* wd = Wd + s*DD*DD;
    const float* wt = Wtau + s*DD*DD;
    float accd = 0.f, acct = 0.f;
    for (int d = 0; d < DD; d++) {
        float w = W_in[f*DD + d];
        accd = fmaf(w, wd[d*DD + e], accd);
        acct = fmaf(w, wt[d*DD + e], acct);
    }
    g_Pd[s][f][e] = accd;
    g_Pt[s][f][e] = acct;
    if (e < NNn) {
        const float* wb = WB + s*DD*NNn;
        const float* wc = WC + s*DD*NNn;
        float aB = 0.f, aC = 0.f;
        for (int d = 0; d < DD; d++) {
            float w = W_in[f*DD + d];
            aB = fmaf(w, wb[d*NNn + e], aB);
            aC = fmaf(w, wc[d*NNn + e], aC);
        }
        g_PB[s][f][e] = aB;
        g_PC[s][f][e] = aC;
    }
    if (f == 0) {
        float ad = bd[s*DD + e], at = 0.f;
        for (int d = 0; d < DD; d++) {
            float bi = b_in[d];
            ad = fmaf(bi, wd[d*DD + e], ad);
            at = fmaf(bi, wt[d*DD + e], at);
        }
        g_pbd[s][e] = ad;
        g_pbt[s][e] = at;
        if (e < NNn) {
            const float* wb = WB + s*DD*NNn;
            const float* wc = WC + s*DD*NNn;
            float aB = 0.f, aC = 0.f;
            for (int d = 0; d < DD; d++) {
                aB = fmaf(b_in[d], wb[d*NNn + e], aB);
                aC = fmaf(b_in[d], wc[d*NNn + e], aC);
            }
            g_pbB[s][e] = aB;
            g_pbC[s][e] = aC;
        }
    }
    if (f == 1) {
        #pragma unroll
        for (int n = 0; n < NNn; n++)
            g_A2[s][e][n] = -expf(A_log[(s*DD + e)*NNn + n]) * LOG2E;
    }
}

// ---------------- kernel 2: main GEMM (K=64) + activation epilogue ----------------
#define TMr 128
#define XPAD 132   // keeps float4 row alignment (132*4 bytes % 16 == 0)

__device__ __forceinline__ float act_fuse(float u, float v) {
    // softplus(u) * sigmoid(v)
    float sp = __logf(1.f + __expf(u));
    float sg = __fdividef(1.f, 1.f + __expf(-v));
    return sp * sg;
}

__global__ void __launch_bounds__(256) main_gemm_kernel(const float* __restrict__ x,
        const float* __restrict__ W_in, const float* __restrict__ b_in)
{
    extern __shared__ float sm[];
    float* xS = sm;                  // [64][XPAD]  x tile, transposed: xS[k][r]
    float* uS = sm + 64*XPAD;        // [64][64]
    float* vS = uS + 64*64;          // [64][64]

    int row0 = blockIdx.x * TMr;
    int task = blockIdx.y;           // 0..13
    int tid  = threadIdx.x;

    // load x tile (128 rows x 64 k), transposed into smem
    for (int i = tid; i < TMr*FF; i += 256) {
        int r = i >> 6, k = i & 63;
        xS[k*XPAD + r] = x[(row0 + r)*FF + k];
    }

    // load weight tile(s)
    if (task < 4) {                     // h = x@W_in + b_in
        int c0 = task*64;
        for (int i = tid; i < 64*64; i += 256) {
            int kk = i >> 6, c = i & 63;
            uS[i] = W_in[kk*DD + c0 + c];
        }
    } else if (task < 12) {             // delta = softplus(x@Pd+pbd)*sigmoid(x@Pt+pbt)
        int dt = task - 4, s = dt >> 2, c0 = (dt & 3)*64;
        for (int i = tid; i < 64*64; i += 256) {
            int kk = i >> 6, c = i & 63;
            uS[i] = g_Pd[s][kk][c0 + c];
            vS[i] = g_Pt[s][kk][c0 + c];
        }
    } else {                            // Bm = x@PB + pbB
        int s = task - 12;
        for (int i = tid; i < 64*NNn; i += 256) {
            uS[i] = g_PB[s][i >> 4][i & 15];
        }
    }
    __syncthreads();

    if (task >= 12) {
        // Bm: 128 rows x 16 cols; thread = (col, 8-row strip)
        int c = tid & 15, rb2 = (tid >> 4) * 8;
        int s = task - 12;
        float acc[8];
        #pragma unroll
        for (int r = 0; r < 8; r++) acc[r] = 0.f;
        #pragma unroll 8
        for (int k = 0; k < 64; k++) {
            float w = uS[k*16 + c];
            const float4* xr4 = (const float4*)(xS + k*XPAD + rb2);
            float4 a0 = xr4[0], a1 = xr4[1];
            acc[0] = fmaf(a0.x, w, acc[0]);
            acc[1] = fmaf(a0.y, w, acc[1]);
            acc[2] = fmaf(a0.z, w, acc[2]);
            acc[3] = fmaf(a0.w, w, acc[3]);
            acc[4] = fmaf(a1.x, w, acc[4]);
            acc[5] = fmaf(a1.y, w, acc[5]);
            acc[6] = fmaf(a1.z, w, acc[6]);
            acc[7] = fmaf(a1.w, w, acc[7]);
        }
        float bias = g_pbB[s][c];
        #pragma unroll
        for (int r = 0; r < 8; r++) {
            int row = row0 + rb2 + r;
            g_Bm[s][row*NNn + c] = acc[r] + bias;
        }
        return;
    }

    int tx = tid & 15, ty = tid >> 4;
    int rb = ty * 8;

    if (task < 4) {
        float4 accU[8];
        #pragma unroll
        for (int r = 0; r < 8; r++) accU[r] = make_float4(0.f,0.f,0.f,0.f);
        #pragma unroll 4
        for (int k = 0; k < 64; k++) {
            const float4* xr = (const float4*)(xS + k*XPAD) + ty*2;
            float4 a0 = xr[0], a1 = xr[1];
            float4 wu = ((const float4*)(uS + k*64))[tx];
            float av[8] = {a0.x,a0.y,a0.z,a0.w,a1.x,a1.y,a1.z,a1.w};
            #pragma unroll
            for (int r = 0; r < 8; r++) {
                accU[r].x = fmaf(av[r], wu.x, accU[r].x);
                accU[r].y = fmaf(av[r], wu.y, accU[r].y);
                accU[r].z = fmaf(av[r], wu.z, accU[r].z);
                accU[r].w = fmaf(av[r], wu.w, accU[r].w);
            }
        }
        int c0 = task*64 + tx*4;
        float4 bv = *(const float4*)(b_in + c0);
        #pragma unroll
        for (int r = 0; r < 8; r++) {
            int row = row0 + rb + r;
            float4 o;
            o.x = accU[r].x + bv.x;
            o.y = accU[r].y + bv.y;
            o.z = accU[r].z + bv.z;
            o.w = accU[r].w + bv.w;
            *(float4*)&g_h[row*DD + c0] = o;
        }
    } else {
        float4 accU[8], accV[8];
        #pragma unroll
        for (int r = 0; r < 8; r++) { accU[r] = make_float4(0.f,0.f,0.f,0.f);
                                      accV[r] = make_float4(0.f,0.f,0.f,0.f); }
        #pragma unroll 2
        for (int k = 0; k < 64; k++) {
            const float4* xr = (const float4*)(xS + k*XPAD) + ty*2;
            float4 a0 = xr[0], a1 = xr[1];
            float4 wu = ((const float4*)(uS + k*64))[tx];
            float4 wv = ((const float4*)(vS + k*64))[tx];
            float av[8] = {a0.x,a0.y,a0.z,a0.w,a1.x,a1.y,a1.z,a1.w};
            #pragma unroll
            for (int r = 0; r < 8; r++) {
                accU[r].x = fmaf(av[r], wu.x, accU[r].x);
                accU[r].y = fmaf(av[r], wu.y, accU[r].y);
                accU[r].z = fmaf(av[r], wu.z, accU[r].z);
                accU[r].w = fmaf(av[r], wu.w, accU[r].w);
                accV[r].x = fmaf(av[r], wv.x, accV[r].x);
                accV[r].y = fmaf(av[r], wv.y, accV[r].y);
                accV[r].z = fmaf(av[r], wv.z, accV[r].z);
                accV[r].w = fmaf(av[r], wv.w, accV[r].w);
            }
        }
        int dt = task - 4, s = dt >> 2;
        int c0 = (dt & 3)*64 + tx*4;
        float4 pu = *(const float4*)&g_pbd[s][c0];
        float4 pv = *(const float4*)&g_pbt[s][c0];
        #pragma unroll
        for (int r = 0; r < 8; r++) {
            int row = row0 + rb + r;
            float4 o;
            o.x = act_fuse(accU[r].x + pu.x, accV[r].x + pv.x);
            o.y = act_fuse(accU[r].y + pu.y, accV[r].y + pv.y);
            o.z = act_fuse(accU[r].z + pu.z, accV[r].z + pv.z);
            o.w = act_fuse(accU[r].w + pu.w, accV[r].w + pv.w);
            *(float4*)&g_delta[s][row*DD + c0] = o;
        }
    }
}

// ---------------- kernel 3: scan (B*D*N chains, both s per thread) ----------------
#define CHn 32
#define SPn 36   // padded: 36*4 bytes keeps float4 alignment; 2-transaction minimum reads

__global__ void __launch_bounds__(256) scan_kernel()
{
    __shared__ __align__(16) float dS[SSn][16][SPn];  // [s][dd][l]
    __shared__ __align__(16) float hS[16][SPn];       // [dd][l]
    __shared__ __align__(16) float bS[SSn][16][SPn];  // [s][nn][l]

    int b  = blockIdx.x >> 4;
    int d0 = (blockIdx.x & 15) * 16;
    int tid = threadIdx.x;
    int dd = tid & 15, nn = tid >> 4;
    int d = d0 + dd;

    float a20 = g_A2[0][d][nn], a21 = g_A2[1][d][nn];
    float st0 = 0.f, st1 = 0.f;

    for (int l0 = 0; l0 < LL; l0 += CHn) {
        __syncthreads();
        for (int i = tid; i < CHn*16; i += 256) {
            int l = i >> 4, q = i & 15;
            int base = b*LL + l0 + l;
            dS[0][q][l] = g_delta[0][base*DD + d0 + q];
            dS[1][q][l] = g_delta[1][base*DD + d0 + q];
            hS[q][l]    = g_h[base*DD + d0 + q];
            bS[0][q][l] = g_Bm[0][base*NNn + q];
            bS[1][q][l] = g_Bm[1][base*NNn + q];
        }
        __syncthreads();
        #pragma unroll
        for (int j = 0; j < CHn/4; j++) {
            float4 d0v = *(const float4*)&dS[0][dd][j*4];
            float4 d1v = *(const float4*)&dS[1][dd][j*4];
            float4 hv  = *(const float4*)&hS[dd][j*4];
            float4 b0v = *(const float4*)&bS[0][nn][j*4];
            float4 b1v = *(const float4*)&bS[1][nn][j*4];
            st0 = fmaf(exp2f(d0v.x*a20), st0, d0v.x*hv.x*b0v.x);
            st1 = fmaf(exp2f(d1v.x*a21), st1, d1v.x*hv.x*b1v.x);
            st0 = fmaf(exp2f(d0v.y*a20), st0, d0v.y*hv.y*b0v.y);
            st1 = fmaf(exp2f(d1v.y*a21), st1, d1v.y*hv.y*b1v.y);
            st0 = fmaf(exp2f(d0v.z*a20), st0, d0v.z*hv.z*b0v.z);
            st1 = fmaf(exp2f(d1v.z*a21), st1, d1v.z*hv.z*b1v.z);
            st0 = fmaf(exp2f(d0v.w*a20), st0, d0v.w*hv.w*b0v.w);
            st1 = fmaf(exp2f(d1v.w*a21), st1, d1v.w*hv.w*b1v.w);
        }
    }
    g_state[0][b][d][nn] = st0;
    g_state[1][b][d][nn] = st1;
}

// ---------------- kernel 4: last-token fusion (Cm, y, Wout, LN, MLP) ----------------
__global__ void __launch_bounds__(256) final_kernel(const float* __restrict__ x,
    const float* __restrict__ Dp, const float* __restrict__ Wout,
    const float* __restrict__ ln_g, const float* __restrict__ ln_b,
    const float* __restrict__ W1, const float* __restrict__ b1,
    const float* __restrict__ W2, const float* __restrict__ b2,
    float* __restrict__ out)
{
    __shared__ float xl[FF];
    __shared__ float CmS[SSn][NNn];
    __shared__ float yS[SSn][DD];
    __shared__ float zS[DD];
    __shared__ float red[8];
    __shared__ float stats[2];

    int b = blockIdx.x;
    int t = threadIdx.x;

    if (t < FF) xl[t] = x[(b*LL + LL-1)*FF + t];
    __syncthreads();
    if (t < SSn*NNn) {
        int s = t >> 4, n = t & 15;
        float acc = g_pbC[s][n];
        #pragma unroll 8
        for (int f = 0; f < FF; f++) acc = fmaf(xl[f], g_PC[s][f][n], acc);
        CmS[s][n] = acc;
    }
    __syncthreads();

    float hl = g_h[(b*LL + LL-1)*DD + t];
    #pragma unroll
    for (int s = 0; s < SSn; s++) {
        float y = hl * Dp[s*DD + t];
        #pragma unroll
        for (int n = 0; n < NNn; n++)
            y = fmaf(g_state[s][b][t][n], CmS[s][n], y);
        yS[s][t] = y;
    }
    __syncthreads();

    float o = 0.f;
    #pragma unroll 2
    for (int s = 0; s < SSn; s++)
        #pragma unroll 8
        for (int k = 0; k < DD; k++)
            o = fmaf(yS[s][k], Wout[(s*DD + k)*DD + t], o);
    o *= 0.5f;

    // layernorm: mean
    float v = o;
    #pragma unroll
    for (int off = 16; off; off >>= 1) v += __shfl_xor_sync(0xffffffffu, v, off);
    if ((t & 31) == 0) red[t >> 5] = v;
    __syncthreads();
    if (t == 0) {
        float sum = 0.f;
        #pragma unroll
        for (int i = 0; i < 8; i++) sum += red[i];
        stats[0] = sum * (1.f/DD);
    }
    __syncthreads();
    float mu = stats[0];
    float dm = o - mu;
    // variance
    v = dm*dm;
    #pragma unroll
    for (int off = 16; off; off >>= 1) v += __shfl_xor_sync(0xffffffffu, v, off);
    if ((t & 31) == 0) red[t >> 5] = v;
    __syncthreads();
    if (t == 0) {
        float sum = 0.f;
        #pragma unroll
        for (int i = 0; i < 8; i++) sum += red[i];
        stats[1] = sum * (1.f/DD);
    }
    __syncthreads();
    float var = stats[1];
    zS[t] = dm * rsqrtf(var + EPSV) * ln_g[t] + ln_b[t];
    __syncthreads();

    if (t < HHn) {
        float a = b1[t];
        #pragma unroll 8
        for (int k = 0; k < DD; k++) a = fmaf(zS[k], W1[k*HHn + t], a);
        a = fmaxf(a, 0.f);
        float p = a * W2[t];
        #pragma unroll
        for (int off = 16; off; off >>= 1) p += __shfl_xor_sync(0xffffffffu, p, off);
        if (t == 0) out[b] = p + b2[0];
    }
}

// ---------------- launch ----------------
extern "C" void kernel_launch(void* const* d_in, const int* in_sizes, int n_in,
                              void* d_out, int out_size)
{
    const float* x     = (const float*)d_in[0];
    const float* W_in  = (const float*)d_in[1];
    const float* b_in  = (const float*)d_in[2];
    const float* Wd    = (const float*)d_in[3];
    const float* bd    = (const float*)d_in[4];
    const float* WB    = (const float*)d_in[5];
    const float* WC    = (const float*)d_in[6];
    const float* Wtau  = (const float*)d_in[7];
    const float* A_log = (const float*)d_in[8];
    const float* Dp    = (const float*)d_in[9];
    const float* Wout  = (const float*)d_in[10];
    const float* ln_g  = (const float*)d_in[11];
    const float* ln_b  = (const float*)d_in[12];
    const float* W1    = (const float*)d_in[13];
    const float* b1    = (const float*)d_in[14];
    const float* W2    = (const float*)d_in[15];
    const float* b2    = (const float*)d_in[16];
    float* out = (float*)d_out;

    precompute_kernel<<<128, 256>>>(W_in, b_in, Wd, bd, WB, WC, Wtau, A_log);

    size_t smem = (size_t)(64*XPAD + 2*64*64) * sizeof(float);  // 66560 B
    cudaFuncSetAttribute(main_gemm_kernel,
                         cudaFuncAttributeMaxDynamicSharedMemorySize, (int)smem);
    main_gemm_kernel<<<dim3(MMn/TMr, 14), 256, smem>>>(x, W_in, b_in);

    scan_kernel<<<BB*16, 256>>>();

    final_kernel<<<BB, 256>>>(x, Dp, Wout, ln_g, ln_b, W1, b1, W2, b2, out);
}